// round 10
// baseline (speedup 1.0000x reference)
#include <cuda_runtime.h>
#include <cuda_bf16.h>
#include <math.h>
#include <stdint.h>

#define Bsz  16
#define Cdim 64
#define Lseq 1024
#define Hn   8
#define HC   512
#define NH   128   // B*H batch-heads

// ---------------- scratch (static device memory; no allocations) ----------------
__device__ float g_PW[1536 * 64];             // packed pointwise weights (q|k|v)
__device__ float g_WF[1536 * 15];             // combined 15-tap depthwise weights
__device__ __nv_bfloat16 g_Q[NH * Lseq * Cdim];  // (n, l, c) bf16, pre-scaled x0.125
__device__ __nv_bfloat16 g_K[NH * Lseq * Cdim];  // (n, l, c) bf16
__device__ __nv_bfloat16 g_V[NH * Cdim * Lseq];  // (n, c, l) bf16
__device__ float g_ATT[Bsz * HC * Lseq];      // (b, hc, l)
__device__ float g_Y[Bsz * Cdim * Lseq];      // after LN1
__device__ float g_H[Bsz * 4 * Cdim * Lseq];  // FFN hidden

__device__ __forceinline__ uint32_t bfpack(float lo, float hi) {
    __nv_bfloat162 h = __floats2bfloat162_rn(lo, hi);
    return *reinterpret_cast<uint32_t*>(&h);
}
__device__ __forceinline__ uint32_t smem_u32(const void* p) {
    uint32_t a;
    asm("{ .reg .u64 t; cvta.to.shared.u64 t, %1; cvt.u32.u64 %0, t; }" : "=r"(a) : "l"(p));
    return a;
}

// D += A(16x16 bf16 row) * B(16x8 bf16 col)
__device__ __forceinline__ void mma_bf16(float* c, const uint32_t* a, uint32_t b0, uint32_t b1) {
    asm volatile(
        "mma.sync.aligned.m16n8k16.row.col.f32.bf16.bf16.f32 "
        "{%0,%1,%2,%3}, {%4,%5,%6,%7}, {%8,%9}, {%0,%1,%2,%3};"
        : "+f"(c[0]), "+f"(c[1]), "+f"(c[2]), "+f"(c[3])
        : "r"(a[0]), "r"(a[1]), "r"(a[2]), "r"(a[3]), "r"(b0), "r"(b1));
}
__device__ __forceinline__ void ldsm4(uint32_t& r0, uint32_t& r1, uint32_t& r2, uint32_t& r3,
                                      uint32_t addr) {
    asm volatile("ldmatrix.sync.aligned.m8n8.x4.shared.b16 {%0,%1,%2,%3}, [%4];"
                 : "=r"(r0), "=r"(r1), "=r"(r2), "=r"(r3) : "r"(addr));
}
#define CP16(dst, src) \
    asm volatile("cp.async.cg.shared.global [%0], [%1], 16;" :: "r"(dst), "l"(src))
#define CP_COMMIT() asm volatile("cp.async.commit_group;" ::: "memory")
#define CP_WAIT1()  asm volatile("cp.async.wait_group 1;" ::: "memory")

// ---------------- K0: fold gate softmax into combined conv weights ----------------
__global__ void combine_kernel(
    const float* __restrict__ pw0, const float* __restrict__ gt0,
    const float* __restrict__ d3_0, const float* __restrict__ d15_0,
    const float* __restrict__ pw1, const float* __restrict__ gt1,
    const float* __restrict__ d3_1, const float* __restrict__ d15_1,
    const float* __restrict__ pw2, const float* __restrict__ gt2,
    const float* __restrict__ d3_2, const float* __restrict__ d15_2,
    float* __restrict__ PW, float* __restrict__ WF)
{
    int o = blockIdx.x * 256 + threadIdx.x;
    if (o >= 1536) return;
    int s = o >> 9, lc = o & 511;
    const float *pw, *gt, *d3, *d15;
    if (s == 0)      { pw = pw0; gt = gt0; d3 = d3_0; d15 = d15_0; }
    else if (s == 1) { pw = pw1; gt = gt1; d3 = d3_1; d15 = d15_1; }
    else             { pw = pw2; gt = gt2; d3 = d3_2; d15 = d15_2; }
    float a = gt[0], b = gt[1];
    float mx = fmaxf(a, b);
    float e0 = expf(a - mx), e1 = expf(b - mx);
    float inv = 1.0f / (e0 + e1);
    float ga = e0 * inv, gb = e1 * inv;
    for (int c = 0; c < 64; c++) PW[(size_t)o * 64 + c] = pw[(size_t)lc * 64 + c];
    for (int t = 0; t < 15; t++) {
        float w = gb * d15[lc * 15 + t];
        if (t >= 6 && t < 9) w += ga * d3[lc * 3 + (t - 6)];
        WF[o * 15 + t] = w;
    }
}

// ---------------- K1: fused pointwise GEMM + depthwise conv15 -> Q/K/V (bf16 out) ----------------
__global__ __launch_bounds__(256) void qkv_kernel(
    const float* __restrict__ q,
    const float* __restrict__ PW, const float* __restrict__ WF,
    __nv_bfloat16* __restrict__ Qp, __nv_bfloat16* __restrict__ Kp,
    __nv_bfloat16* __restrict__ Vp)
{
    extern __shared__ float sm1[];
    float* xs  = sm1;               // [64][144]
    float* mid = xs + 64 * 144;     // [32][144]
    float* spw = mid + 32 * 144;    // [32][64]
    float* swf = spw + 32 * 64;     // [32][16]
    int tid = threadIdx.x;
    int l0 = blockIdx.x * 128;
    int o0 = blockIdx.y * 32;
    int b  = blockIdx.z;

    for (int e = tid; e < 64 * 144; e += 256) {
        int c = e / 144, j = e - c * 144;
        int gl = l0 - 7 + j;
        float v = 0.f;
        if (gl >= 0 && gl < Lseq) v = q[((size_t)b * 64 + c) * Lseq + gl];
        xs[c * 144 + j] = v;
    }
    for (int e = tid; e < 32 * 64; e += 256) spw[e] = PW[(size_t)o0 * 64 + e];
    for (int e = tid; e < 32 * 15; e += 256) {
        int o = e / 15, t = e - o * 15;
        swf[o * 16 + t] = WF[(size_t)(o0 + o) * 15 + t];
    }
    __syncthreads();

    for (int e = tid; e < 32 * 36; e += 256) {
        int o = e / 36, jq = e - o * 36;
        const float* pwrow = spw + o * 64;
        const float* xcol  = xs + jq * 4;
        float4 acc = make_float4(0.f, 0.f, 0.f, 0.f);
#pragma unroll 8
        for (int c = 0; c < 64; c++) {
            float w = pwrow[c];
            float4 xv = *(const float4*)(xcol + c * 144);
            acc.x += w * xv.x; acc.y += w * xv.y; acc.z += w * xv.z; acc.w += w * xv.w;
        }
        *(float4*)(mid + o * 144 + jq * 4) = acc;
    }
    __syncthreads();

    int s = o0 >> 9;
    float scale = (s == 0) ? 0.125f : 1.0f;
    for (int e = tid; e < 32 * 128; e += 256) {
        int o = e >> 7, i = e & 127;
        const float* mrow = mid + o * 144;
        const float* wrow = swf + o * 16;
        float acc = 0.f;
#pragma unroll
        for (int t = 0; t < 15; t++) acc += wrow[t] * mrow[i + t];
        acc *= scale;
        int og = o0 + o;
        int ch = og & 511;
        int head = ch >> 6, c = ch & 63;
        size_t n = (size_t)b * 8 + head;
        __nv_bfloat16 hv = __float2bfloat16_rn(acc);
        if (s == 2) {
            Vp[(n * 64 + c) * Lseq + l0 + i] = hv;                  // (n, c, l)
        } else {
            __nv_bfloat16* base = (s == 0) ? Qp : Kp;
            base[(n * Lseq + l0 + i) * 64 + c] = hv;                // (n, l, c)
        }
    }
}

// ---------------- K2: flash attention: bf16 mma + ldmatrix + cp.async double buffer ----------------
// grid (8, 128); 256 threads (8 warps x 16 q-rows). static smem 36864 B.
#define KVS 72              // padded row stride (bf16 elems); 144 B
#define BUFE (64 * KVS)     // elems per buffer
__global__ __launch_bounds__(256, 2) void attn_bf16(
    const __nv_bfloat16* __restrict__ Qt, const __nv_bfloat16* __restrict__ Kt,
    const __nv_bfloat16* __restrict__ Vg, float* __restrict__ att)
{
    __shared__ __nv_bfloat16 Ks[2][BUFE];
    __shared__ __nv_bfloat16 Vs[2][BUFE];
    int tid = threadIdx.x, w = tid >> 5, lane = tid & 31;
    int g = lane >> 2, r = lane & 3;
    int n = blockIdx.y, q0 = blockIdx.x * 128;

    const __nv_bfloat16* Qb = Qt + (size_t)n * (Lseq * 64) + (size_t)(q0 + w * 16) * 64;
    const __nv_bfloat16* Kb = Kt + (size_t)n * (Lseq * 64);
    const __nv_bfloat16* Vb = Vg + (size_t)n * (64 * Lseq);

    int kr0 = tid >> 3, kg0 = tid & 7;
    int kr1 = (tid + 256) >> 3, kg1 = (tid + 256) & 7;
    uint32_t ks_base = smem_u32(&Ks[0][0]);
    uint32_t vs_base = smem_u32(&Vs[0][0]);
    uint32_t kd0 = ks_base + (kr0 * KVS + kg0 * 8) * 2;
    uint32_t kd1 = ks_base + (kr1 * KVS + kg1 * 8) * 2;
    uint32_t vd0 = vs_base + (kr0 * KVS + kg0 * 8) * 2;
    uint32_t vd1 = vs_base + (kr1 * KVS + kg1 * 8) * 2;

    int sel = lane >> 3, lrow = lane & 7;
    int mrow = ((sel >> 1) << 3) + lrow;
    int mcol = (sel & 1) << 3;
    uint32_t kls = ks_base + (mrow * KVS + mcol) * 2;
    uint32_t vls = vs_base + (mrow * KVS + mcol) * 2;

    uint32_t qf[16];
#pragma unroll
    for (int kc = 0; kc < 4; kc++) {
        qf[kc * 4 + 0] = *(const uint32_t*)(Qb + (size_t)g * 64 + kc * 16 + 2 * r);
        qf[kc * 4 + 1] = *(const uint32_t*)(Qb + (size_t)(g + 8) * 64 + kc * 16 + 2 * r);
        qf[kc * 4 + 2] = *(const uint32_t*)(Qb + (size_t)g * 64 + kc * 16 + 2 * r + 8);
        qf[kc * 4 + 3] = *(const uint32_t*)(Qb + (size_t)(g + 8) * 64 + kc * 16 + 2 * r + 8);
    }

#pragma unroll
    for (int t = 0; t < 2; t++) {
        int k0 = t * 64;
        uint32_t bo = t * BUFE * 2;
        CP16(kd0 + bo, Kb + (size_t)(k0 + kr0) * 64 + kg0 * 8);
        CP16(kd1 + bo, Kb + (size_t)(k0 + kr1) * 64 + kg1 * 8);
        CP16(vd0 + bo, Vb + (size_t)kr0 * Lseq + k0 + kg0 * 8);
        CP16(vd1 + bo, Vb + (size_t)kr1 * Lseq + k0 + kg1 * 8);
        CP_COMMIT();
    }

    float oacc[32];
#pragma unroll
    for (int i = 0; i < 32; i++) oacc[i] = 0.f;
    float m0 = -INFINITY, m1 = -INFINITY, l0 = 0.f, l1 = 0.f;

    for (int kt = 0; kt < 16; kt++) {
        CP_WAIT1();
        __syncthreads();
        uint32_t bo = (kt & 1) * BUFE * 2;

        float sacc[32];
#pragma unroll
        for (int i = 0; i < 32; i++) sacc[i] = 0.f;
#pragma unroll
        for (int kc = 0; kc < 4; kc++) {
#pragma unroll
            for (int nb2 = 0; nb2 < 4; nb2++) {
                uint32_t b0, b1, b2, b3;
                ldsm4(b0, b1, b2, b3, kls + bo + nb2 * (16 * KVS * 2) + kc * 32);
                mma_bf16(sacc + (2 * nb2) * 4,     qf + kc * 4, b0, b1);
                mma_bf16(sacc + (2 * nb2 + 1) * 4, qf + kc * 4, b2, b3);
            }
        }

        float tm0 = -INFINITY, tm1 = -INFINITY;
#pragma unroll
        for (int nb = 0; nb < 8; nb++) {
            tm0 = fmaxf(tm0, fmaxf(sacc[nb * 4 + 0], sacc[nb * 4 + 1]));
            tm1 = fmaxf(tm1, fmaxf(sacc[nb * 4 + 2], sacc[nb * 4 + 3]));
        }
        tm0 = fmaxf(tm0, __shfl_xor_sync(0xffffffffu, tm0, 1));
        tm0 = fmaxf(tm0, __shfl_xor_sync(0xffffffffu, tm0, 2));
        tm1 = fmaxf(tm1, __shfl_xor_sync(0xffffffffu, tm1, 1));
        tm1 = fmaxf(tm1, __shfl_xor_sync(0xffffffffu, tm1, 2));
        float mn0 = fmaxf(m0, tm0), mn1 = fmaxf(m1, tm1);
        float al0 = __expf(m0 - mn0), al1 = __expf(m1 - mn1);
        m0 = mn0; m1 = mn1;
        float s0 = 0.f, s1 = 0.f;
        uint32_t plo[8], phi[8];
#pragma unroll
        for (int nb = 0; nb < 8; nb++) {
            float p0 = __expf(sacc[nb * 4 + 0] - mn0);
            float p1 = __expf(sacc[nb * 4 + 1] - mn0);
            float p2 = __expf(sacc[nb * 4 + 2] - mn1);
            float p3 = __expf(sacc[nb * 4 + 3] - mn1);
            s0 += p0 + p1; s1 += p2 + p3;
            plo[nb] = bfpack(p0, p1);
            phi[nb] = bfpack(p2, p3);
        }
        s0 += __shfl_xor_sync(0xffffffffu, s0, 1);
        s0 += __shfl_xor_sync(0xffffffffu, s0, 2);
        s1 += __shfl_xor_sync(0xffffffffu, s1, 1);
        s1 += __shfl_xor_sync(0xffffffffu, s1, 2);
        l0 = l0 * al0 + s0;
        l1 = l1 * al1 + s1;
#pragma unroll
        for (int nb = 0; nb < 8; nb++) {
            oacc[nb * 4 + 0] *= al0; oacc[nb * 4 + 1] *= al0;
            oacc[nb * 4 + 2] *= al1; oacc[nb * 4 + 3] *= al1;
        }

#pragma unroll
        for (int kc = 0; kc < 4; kc++) {
            uint32_t pa[4] = {plo[2 * kc], phi[2 * kc], plo[2 * kc + 1], phi[2 * kc + 1]};
#pragma unroll
            for (int nb2 = 0; nb2 < 4; nb2++) {
                uint32_t b0, b1, b2, b3;
                ldsm4(b0, b1, b2, b3, vls + bo + nb2 * (16 * KVS * 2) + kc * 32);
                mma_bf16(oacc + (2 * nb2) * 4,     pa, b0, b1);
                mma_bf16(oacc + (2 * nb2 + 1) * 4, pa, b2, b3);
            }
        }

        __syncthreads();
        if (kt < 14) {
            int k0 = (kt + 2) * 64;
            uint32_t nb_ = (kt & 1) * BUFE * 2;
            CP16(kd0 + nb_, Kb + (size_t)(k0 + kr0) * 64 + kg0 * 8);
            CP16(kd1 + nb_, Kb + (size_t)(k0 + kr1) * 64 + kg1 * 8);
            CP16(vd0 + nb_, Vb + (size_t)kr0 * Lseq + k0 + kg0 * 8);
            CP16(vd1 + nb_, Vb + (size_t)kr1 * Lseq + k0 + kg1 * 8);
        }
        CP_COMMIT();
    }

    float inv0 = 1.0f / l0, inv1 = 1.0f / l1;
    int bb = n >> 3, head = n & 7;
    int qg0 = q0 + w * 16 + g, qg1 = qg0 + 8;
    float* ab = att + ((size_t)bb * 512 + head * 64) * Lseq;
#pragma unroll
    for (int nb = 0; nb < 8; nb++) {
        int c = nb * 8 + 2 * r;
        ab[(size_t)c * Lseq + qg0]       = oacc[nb * 4 + 0] * inv0;
        ab[(size_t)(c + 1) * Lseq + qg0] = oacc[nb * 4 + 1] * inv0;
        ab[(size_t)c * Lseq + qg1]       = oacc[nb * 4 + 2] * inv1;
        ab[(size_t)(c + 1) * Lseq + qg1] = oacc[nb * 4 + 3] * inv1;
    }
}

// ---------------- K3/K5: (64 out x INC) GEMM + bias + residual + channel LN, L-tile 32 ----------------
// grid (32, 16); 256 threads; ty=tid>>3 (2 outputs), tx=tid&7 (4 L)
__global__ __launch_bounds__(256) void gemm_res_ln_kernel(
    const float* __restrict__ X, const float* __restrict__ W,
    const float* __restrict__ bias, const float* __restrict__ res,
    const float* __restrict__ gam, const float* __restrict__ bet,
    float* __restrict__ out, int INC)
{
    __shared__ float sx[64 * 36];
    __shared__ float sw[64 * 68];
    int tid = threadIdx.x;
    int l0 = blockIdx.x * 32;
    int b  = blockIdx.y;
    int ty = tid >> 3, tx = tid & 7;
    float acc[2][4];
#pragma unroll
    for (int i = 0; i < 2; i++)
#pragma unroll
        for (int j = 0; j < 4; j++) acc[i][j] = 0.f;

    for (int cb = 0; cb < INC; cb += 64) {
        __syncthreads();
        // sx: 64 ci x 32 L (2 float4 per thread)
#pragma unroll
        for (int f = tid; f < 512; f += 256) {
            int ci = f >> 3, lg = f & 7;
            *(float4*)(sx + ci * 36 + lg * 4) =
                *(const float4*)(X + ((size_t)b * INC + cb + ci) * Lseq + l0 + lg * 4);
        }
        // sw: 64 ci x 64 out
        for (int e = tid; e < 4096; e += 256) {
            int o = e >> 6, ci = e & 63;
            sw[ci * 68 + o] = W[(size_t)o * INC + cb + ci];
        }
        __syncthreads();
#pragma unroll 8
        for (int ci = 0; ci < 64; ci++) {
            float2 wv = *(const float2*)(sw + ci * 68 + ty * 2);
            float4 xv = *(const float4*)(sx + ci * 36 + tx * 4);
            acc[0][0] += wv.x * xv.x; acc[0][1] += wv.x * xv.y;
            acc[0][2] += wv.x * xv.z; acc[0][3] += wv.x * xv.w;
            acc[1][0] += wv.y * xv.x; acc[1][1] += wv.y * xv.y;
            acc[1][2] += wv.y * xv.z; acc[1][3] += wv.y * xv.w;
        }
    }
    int lx = tx * 4;
    float vals[2][4];
#pragma unroll
    for (int i = 0; i < 2; i++) {
        int o = ty * 2 + i;
        float bo = bias[o];
        float4 rv = *(const float4*)(res + ((size_t)b * 64 + o) * Lseq + l0 + lx);
        vals[i][0] = acc[i][0] + bo + rv.x;
        vals[i][1] = acc[i][1] + bo + rv.y;
        vals[i][2] = acc[i][2] + bo + rv.z;
        vals[i][3] = acc[i][3] + bo + rv.w;
    }
    __syncthreads();             // sw reusable
    float* red1 = sw;            // [32 ty][32 L]
    float* red2 = sw + 1024;
    float* mu_s = sw + 2048;     // [32]
    float* iv_s = sw + 2080;     // [32]
#pragma unroll
    for (int j = 0; j < 4; j++) {
        red1[ty * 32 + lx + j] = vals[0][j] + vals[1][j];
        red2[ty * 32 + lx + j] = vals[0][j] * vals[0][j] + vals[1][j] * vals[1][j];
    }
    __syncthreads();
    if (tid < 32) {
        float s1 = 0.f, s2 = 0.f;
#pragma unroll
        for (int t = 0; t < 32; t++) { s1 += red1[t * 32 + tid]; s2 += red2[t * 32 + tid]; }
        float mu = s1 * (1.0f / 64.0f);
        float var = s2 * (1.0f / 64.0f) - mu * mu;
        mu_s[tid] = mu;
        iv_s[tid] = rsqrtf(var + 1e-5f);
    }
    __syncthreads();
#pragma unroll
    for (int i = 0; i < 2; i++) {
        int o = ty * 2 + i;
        float gg = gam[o], bb = bet[o];
        float4 ov;
        ov.x = (vals[i][0] - mu_s[lx + 0]) * iv_s[lx + 0] * gg + bb;
        ov.y = (vals[i][1] - mu_s[lx + 1]) * iv_s[lx + 1] * gg + bb;
        ov.z = (vals[i][2] - mu_s[lx + 2]) * iv_s[lx + 2] * gg + bb;
        ov.w = (vals[i][3] - mu_s[lx + 3]) * iv_s[lx + 3] * gg + bb;
        *(float4*)(out + ((size_t)b * 64 + o) * Lseq + l0 + lx) = ov;
    }
}

// ---------------- K4: FFN up-projection (256x64) + bias + ReLU ----------------
__global__ __launch_bounds__(256) void ffn1_kernel(
    const float* __restrict__ X, const float* __restrict__ W,
    const float* __restrict__ bias, float* __restrict__ out)
{
    __shared__ float sx[64 * 68];
    __shared__ float sw[64 * 68];
    int tid = threadIdx.x;
    int l0  = blockIdx.x * 64;
    int ob0 = blockIdx.y * 64;
    int b   = blockIdx.z;
    int ty = tid >> 4, tx = tid & 15;
    float acc[4][4];
#pragma unroll
    for (int i = 0; i < 4; i++)
#pragma unroll
        for (int j = 0; j < 4; j++) acc[i][j] = 0.f;

    for (int e = tid * 4; e < 4096; e += 1024) {
        int ci = e >> 6, l = e & 63;
        *(float4*)(sx + ci * 68 + l) =
            *(const float4*)(X + ((size_t)b * 64 + ci) * Lseq + l0 + l);
    }
    for (int e = tid; e < 4096; e += 256) {
        int o = e >> 6, ci = e & 63;
        sw[ci * 68 + o] = W[(size_t)(ob0 + o) * 64 + ci];
    }
    __syncthreads();
#pragma unroll 4
    for (int ci = 0; ci < 64; ci++) {
        float4 wv = *(const float4*)(sw + ci * 68 + ty * 4);
        float4 xv = *(const float4*)(sx + ci * 68 + tx * 4);
        float wr[4] = {wv.x, wv.y, wv.z, wv.w};
        float xr[4] = {xv.x, xv.y, xv.z, xv.w};
#pragma unroll
        for (int i = 0; i < 4; i++)
#pragma unroll
            for (int j = 0; j < 4; j++) acc[i][j] += wr[i] * xr[j];
    }
    int lx = tx * 4;
#pragma unroll
    for (int i = 0; i < 4; i++) {
        int o = ob0 + ty * 4 + i;
        float bo = bias[o];
        float4 ov;
        ov.x = fmaxf(acc[i][0] + bo, 0.f);
        ov.y = fmaxf(acc[i][1] + bo, 0.f);
        ov.z = fmaxf(acc[i][2] + bo, 0.f);
        ov.w = fmaxf(acc[i][3] + bo, 0.f);
        *(float4*)(out + ((size_t)b * 256 + o) * Lseq + l0 + lx) = ov;
    }
}

// ---------------- launch ----------------
extern "C" void kernel_launch(void* const* d_in, const int* in_sizes, int n_in,
                              void* d_out, int out_size)
{
    const float* q       = (const float*)d_in[0];
    const float* wq_pw   = (const float*)d_in[1];
    const float* wq_gate = (const float*)d_in[2];
    const float* wq_dw3  = (const float*)d_in[3];
    const float* wq_dw15 = (const float*)d_in[4];
    const float* wk_pw   = (const float*)d_in[5];
    const float* wk_gate = (const float*)d_in[6];
    const float* wk_dw3  = (const float*)d_in[7];
    const float* wk_dw15 = (const float*)d_in[8];
    const float* wv_pw   = (const float*)d_in[9];
    const float* wv_gate = (const float*)d_in[10];
    const float* wv_dw3  = (const float*)d_in[11];
    const float* wv_dw15 = (const float*)d_in[12];
    const float* w_unify = (const float*)d_in[13];
    const float* b_unify = (const float*)d_in[14];
    const float* ln1_g   = (const float*)d_in[15];
    const float* ln1_b   = (const float*)d_in[16];
    const float* ln2_g   = (const float*)d_in[17];
    const float* ln2_b   = (const float*)d_in[18];
    const float* ffn_w1  = (const float*)d_in[19];
    const float* ffn_b1  = (const float*)d_in[20];
    const float* ffn_w2  = (const float*)d_in[21];
    const float* ffn_b2  = (const float*)d_in[22];
    float* out = (float*)d_out;

    void *pPW, *pWF, *pQ, *pK, *pV, *pATT, *pY, *pH;
    cudaGetSymbolAddress(&pPW, g_PW);
    cudaGetSymbolAddress(&pWF, g_WF);
    cudaGetSymbolAddress(&pQ, g_Q);
    cudaGetSymbolAddress(&pK, g_K);
    cudaGetSymbolAddress(&pV, g_V);
    cudaGetSymbolAddress(&pATT, g_ATT);
    cudaGetSymbolAddress(&pY, g_Y);
    cudaGetSymbolAddress(&pH, g_H);

    cudaFuncSetAttribute(qkv_kernel, cudaFuncAttributeMaxDynamicSharedMemorySize, 65536);

    combine_kernel<<<6, 256>>>(
        wq_pw, wq_gate, wq_dw3, wq_dw15,
        wk_pw, wk_gate, wk_dw3, wk_dw15,
        wv_pw, wv_gate, wv_dw3, wv_dw15,
        (float*)pPW, (float*)pWF);

    qkv_kernel<<<dim3(8, 48, 16), 256, 65536>>>(
        q, (const float*)pPW, (const float*)pWF,
        (__nv_bfloat16*)pQ, (__nv_bfloat16*)pK, (__nv_bfloat16*)pV);

    attn_bf16<<<dim3(8, 128), 256>>>(
        (const __nv_bfloat16*)pQ, (const __nv_bfloat16*)pK,
        (const __nv_bfloat16*)pV, (float*)pATT);

    gemm_res_ln_kernel<<<dim3(32, 16), 256>>>(
        (const float*)pATT, w_unify, b_unify, q, ln1_g, ln1_b, (float*)pY, 512);

    ffn1_kernel<<<dim3(16, 4, 16), 256>>>(
        (const float*)pY, ffn_w1, ffn_b1, (float*)pH);

    gemm_res_ln_kernel<<<dim3(32, 16), 256>>>(
        (const float*)pH, ffn_w2, ffn_b2, (const float*)pY, ln2_g, ln2_b, out, 256);
}

// round 11
// speedup vs baseline: 1.1229x; 1.1229x over previous
#include <cuda_runtime.h>
#include <cuda_bf16.h>
#include <math.h>
#include <stdint.h>

#define Bsz  16
#define Cdim 64
#define Lseq 1024
#define Hn   8
#define HC   512
#define NH   128   // B*H batch-heads

// ---------------- scratch (static device memory; no allocations) ----------------
__device__ float g_PW[1536 * 64];
__device__ float g_WF[1536 * 15];
__device__ __nv_bfloat16 g_Q[NH * Lseq * Cdim];   // (n, l, c) bf16, pre-scaled x0.125
__device__ __nv_bfloat16 g_K[NH * Lseq * Cdim];   // (n, l, c) bf16
__device__ __nv_bfloat16 g_V[NH * Cdim * Lseq];   // (n, c, l) bf16
__device__ __nv_bfloat16 g_ATT[Bsz * Lseq * HC];  // (b, l, hc) bf16
__device__ float g_Y[Bsz * Cdim * Lseq];          // LN1 out fp32 (b, c, l)
__device__ __nv_bfloat16 g_Yh[Bsz * Lseq * Cdim]; // LN1 out bf16 (b, l, c)
__device__ __nv_bfloat16 g_H[Bsz * Lseq * 256];   // FFN hidden bf16 (b, l, 256)
__device__ __nv_bfloat16 g_Wu[64 * 512];          // bf16 weights
__device__ __nv_bfloat16 g_W1[256 * 64];
__device__ __nv_bfloat16 g_W2[64 * 256];

__device__ __forceinline__ uint32_t bfpack(float lo, float hi) {
    __nv_bfloat162 h = __floats2bfloat162_rn(lo, hi);
    return *reinterpret_cast<uint32_t*>(&h);
}
__device__ __forceinline__ uint32_t smem_u32(const void* p) {
    uint32_t a;
    asm("{ .reg .u64 t; cvta.to.shared.u64 t, %1; cvt.u32.u64 %0, t; }" : "=r"(a) : "l"(p));
    return a;
}
__device__ __forceinline__ void mma_bf16(float* c, const uint32_t* a, uint32_t b0, uint32_t b1) {
    asm volatile(
        "mma.sync.aligned.m16n8k16.row.col.f32.bf16.bf16.f32 "
        "{%0,%1,%2,%3}, {%4,%5,%6,%7}, {%8,%9}, {%0,%1,%2,%3};"
        : "+f"(c[0]), "+f"(c[1]), "+f"(c[2]), "+f"(c[3])
        : "r"(a[0]), "r"(a[1]), "r"(a[2]), "r"(a[3]), "r"(b0), "r"(b1));
}
__device__ __forceinline__ void ldsm4(uint32_t& r0, uint32_t& r1, uint32_t& r2, uint32_t& r3,
                                      uint32_t addr) {
    asm volatile("ldmatrix.sync.aligned.m8n8.x4.shared.b16 {%0,%1,%2,%3}, [%4];"
                 : "=r"(r0), "=r"(r1), "=r"(r2), "=r"(r3) : "r"(addr));
}
#define CP16(dst, src) \
    asm volatile("cp.async.cg.shared.global [%0], [%1], 16;" :: "r"(dst), "l"(src))
#define CP_COMMIT() asm volatile("cp.async.commit_group;" ::: "memory")
#define CP_WAIT1()  asm volatile("cp.async.wait_group 1;" ::: "memory")

// ---------------- K0: fold gate softmax into combined conv weights ----------------
__global__ void combine_kernel(
    const float* __restrict__ pw0, const float* __restrict__ gt0,
    const float* __restrict__ d3_0, const float* __restrict__ d15_0,
    const float* __restrict__ pw1, const float* __restrict__ gt1,
    const float* __restrict__ d3_1, const float* __restrict__ d15_1,
    const float* __restrict__ pw2, const float* __restrict__ gt2,
    const float* __restrict__ d3_2, const float* __restrict__ d15_2,
    float* __restrict__ PW, float* __restrict__ WF)
{
    int o = blockIdx.x * 256 + threadIdx.x;
    if (o >= 1536) return;
    int s = o >> 9, lc = o & 511;
    const float *pw, *gt, *d3, *d15;
    if (s == 0)      { pw = pw0; gt = gt0; d3 = d3_0; d15 = d15_0; }
    else if (s == 1) { pw = pw1; gt = gt1; d3 = d3_1; d15 = d15_1; }
    else             { pw = pw2; gt = gt2; d3 = d3_2; d15 = d15_2; }
    float a = gt[0], b = gt[1];
    float mx = fmaxf(a, b);
    float e0 = expf(a - mx), e1 = expf(b - mx);
    float inv = 1.0f / (e0 + e1);
    float ga = e0 * inv, gb = e1 * inv;
    for (int c = 0; c < 64; c++) PW[(size_t)o * 64 + c] = pw[(size_t)lc * 64 + c];
    for (int t = 0; t < 15; t++) {
        float w = gb * d15[lc * 15 + t];
        if (t >= 6 && t < 9) w += ga * d3[lc * 3 + (t - 6)];
        WF[o * 15 + t] = w;
    }
}

// ---------------- K0b: convert GEMM weights to bf16 ----------------
__global__ void convw_kernel(const float* __restrict__ wu, const float* __restrict__ w1,
                             const float* __restrict__ w2)
{
    int i = blockIdx.x * 256 + threadIdx.x;
    if (i < 32768)       g_Wu[i] = __float2bfloat16_rn(wu[i]);
    else if (i < 49152)  g_W1[i - 32768] = __float2bfloat16_rn(w1[i - 32768]);
    else if (i < 65536)  g_W2[i - 49152] = __float2bfloat16_rn(w2[i - 49152]);
}

// ---------------- K1: fused pointwise GEMM + depthwise conv15 -> Q/K/V (bf16 out) ----------------
__global__ __launch_bounds__(256) void qkv_kernel(
    const float* __restrict__ q,
    const float* __restrict__ PW, const float* __restrict__ WF,
    __nv_bfloat16* __restrict__ Qp, __nv_bfloat16* __restrict__ Kp,
    __nv_bfloat16* __restrict__ Vp)
{
    extern __shared__ float sm1[];
    float* xs  = sm1;               // [64][144]
    float* mid = xs + 64 * 144;     // [32][144]
    float* spw = mid + 32 * 144;    // [32][64]
    float* swf = spw + 32 * 64;     // [32][16]
    int tid = threadIdx.x;
    int l0 = blockIdx.x * 128;
    int o0 = blockIdx.y * 32;
    int b  = blockIdx.z;

    for (int e = tid; e < 64 * 144; e += 256) {
        int c = e / 144, j = e - c * 144;
        int gl = l0 - 7 + j;
        float v = 0.f;
        if (gl >= 0 && gl < Lseq) v = q[((size_t)b * 64 + c) * Lseq + gl];
        xs[c * 144 + j] = v;
    }
    for (int e = tid; e < 32 * 64; e += 256) spw[e] = PW[(size_t)o0 * 64 + e];
    for (int e = tid; e < 32 * 15; e += 256) {
        int o = e / 15, t = e - o * 15;
        swf[o * 16 + t] = WF[(size_t)(o0 + o) * 15 + t];
    }
    __syncthreads();

    for (int e = tid; e < 32 * 36; e += 256) {
        int o = e / 36, jq = e - o * 36;
        const float* pwrow = spw + o * 64;
        const float* xcol  = xs + jq * 4;
        float4 acc = make_float4(0.f, 0.f, 0.f, 0.f);
#pragma unroll 8
        for (int c = 0; c < 64; c++) {
            float w = pwrow[c];
            float4 xv = *(const float4*)(xcol + c * 144);
            acc.x += w * xv.x; acc.y += w * xv.y; acc.z += w * xv.z; acc.w += w * xv.w;
        }
        *(float4*)(mid + o * 144 + jq * 4) = acc;
    }
    __syncthreads();

    int s = o0 >> 9;
    float scale = (s == 0) ? 0.125f : 1.0f;
    for (int e = tid; e < 32 * 128; e += 256) {
        int o = e >> 7, i = e & 127;
        const float* mrow = mid + o * 144;
        const float* wrow = swf + o * 16;
        float acc = 0.f;
#pragma unroll
        for (int t = 0; t < 15; t++) acc += wrow[t] * mrow[i + t];
        acc *= scale;
        int og = o0 + o;
        int ch = og & 511;
        int head = ch >> 6, c = ch & 63;
        size_t n = (size_t)b * 8 + head;
        __nv_bfloat16 hv = __float2bfloat16_rn(acc);
        if (s == 2) {
            Vp[(n * 64 + c) * Lseq + l0 + i] = hv;                  // (n, c, l)
        } else {
            __nv_bfloat16* base = (s == 0) ? Qp : Kp;
            base[(n * Lseq + l0 + i) * 64 + c] = hv;                // (n, l, c)
        }
    }
}

// ---------------- K2: flash attention (unchanged core; bf16 (b,l,hc) output) ----------------
#define KVS 72
#define BUFE (64 * KVS)
__global__ __launch_bounds__(256, 2) void attn_bf16(
    const __nv_bfloat16* __restrict__ Qt, const __nv_bfloat16* __restrict__ Kt,
    const __nv_bfloat16* __restrict__ Vg, __nv_bfloat16* __restrict__ att)
{
    __shared__ __nv_bfloat16 Ks[2][BUFE];
    __shared__ __nv_bfloat16 Vs[2][BUFE];
    int tid = threadIdx.x, w = tid >> 5, lane = tid & 31;
    int g = lane >> 2, r = lane & 3;
    int n = blockIdx.y, q0 = blockIdx.x * 128;

    const __nv_bfloat16* Qb = Qt + (size_t)n * (Lseq * 64) + (size_t)(q0 + w * 16) * 64;
    const __nv_bfloat16* Kb = Kt + (size_t)n * (Lseq * 64);
    const __nv_bfloat16* Vb = Vg + (size_t)n * (64 * Lseq);

    int kr0 = tid >> 3, kg0 = tid & 7;
    int kr1 = (tid + 256) >> 3, kg1 = (tid + 256) & 7;
    uint32_t ks_base = smem_u32(&Ks[0][0]);
    uint32_t vs_base = smem_u32(&Vs[0][0]);
    uint32_t kd0 = ks_base + (kr0 * KVS + kg0 * 8) * 2;
    uint32_t kd1 = ks_base + (kr1 * KVS + kg1 * 8) * 2;
    uint32_t vd0 = vs_base + (kr0 * KVS + kg0 * 8) * 2;
    uint32_t vd1 = vs_base + (kr1 * KVS + kg1 * 8) * 2;

    int sel = lane >> 3, lrow = lane & 7;
    int mrow = ((sel >> 1) << 3) + lrow;
    int mcol = (sel & 1) << 3;
    uint32_t kls = ks_base + (mrow * KVS + mcol) * 2;
    uint32_t vls = vs_base + (mrow * KVS + mcol) * 2;

    uint32_t qf[16];
#pragma unroll
    for (int kc = 0; kc < 4; kc++) {
        qf[kc * 4 + 0] = *(const uint32_t*)(Qb + (size_t)g * 64 + kc * 16 + 2 * r);
        qf[kc * 4 + 1] = *(const uint32_t*)(Qb + (size_t)(g + 8) * 64 + kc * 16 + 2 * r);
        qf[kc * 4 + 2] = *(const uint32_t*)(Qb + (size_t)g * 64 + kc * 16 + 2 * r + 8);
        qf[kc * 4 + 3] = *(const uint32_t*)(Qb + (size_t)(g + 8) * 64 + kc * 16 + 2 * r + 8);
    }

#pragma unroll
    for (int t = 0; t < 2; t++) {
        int k0 = t * 64;
        uint32_t bo = t * BUFE * 2;
        CP16(kd0 + bo, Kb + (size_t)(k0 + kr0) * 64 + kg0 * 8);
        CP16(kd1 + bo, Kb + (size_t)(k0 + kr1) * 64 + kg1 * 8);
        CP16(vd0 + bo, Vb + (size_t)kr0 * Lseq + k0 + kg0 * 8);
        CP16(vd1 + bo, Vb + (size_t)kr1 * Lseq + k0 + kg1 * 8);
        CP_COMMIT();
    }

    float oacc[32];
#pragma unroll
    for (int i = 0; i < 32; i++) oacc[i] = 0.f;
    float m0 = -INFINITY, m1 = -INFINITY, l0 = 0.f, l1 = 0.f;

    for (int kt = 0; kt < 16; kt++) {
        CP_WAIT1();
        __syncthreads();
        uint32_t bo = (kt & 1) * BUFE * 2;

        float sacc[32];
#pragma unroll
        for (int i = 0; i < 32; i++) sacc[i] = 0.f;
#pragma unroll
        for (int kc = 0; kc < 4; kc++) {
#pragma unroll
            for (int nb2 = 0; nb2 < 4; nb2++) {
                uint32_t b0, b1, b2, b3;
                ldsm4(b0, b1, b2, b3, kls + bo + nb2 * (16 * KVS * 2) + kc * 32);
                mma_bf16(sacc + (2 * nb2) * 4,     qf + kc * 4, b0, b1);
                mma_bf16(sacc + (2 * nb2 + 1) * 4, qf + kc * 4, b2, b3);
            }
        }

        float tm0 = -INFINITY, tm1 = -INFINITY;
#pragma unroll
        for (int nb = 0; nb < 8; nb++) {
            tm0 = fmaxf(tm0, fmaxf(sacc[nb * 4 + 0], sacc[nb * 4 + 1]));
            tm1 = fmaxf(tm1, fmaxf(sacc[nb * 4 + 2], sacc[nb * 4 + 3]));
        }
        tm0 = fmaxf(tm0, __shfl_xor_sync(0xffffffffu, tm0, 1));
        tm0 = fmaxf(tm0, __shfl_xor_sync(0xffffffffu, tm0, 2));
        tm1 = fmaxf(tm1, __shfl_xor_sync(0xffffffffu, tm1, 1));
        tm1 = fmaxf(tm1, __shfl_xor_sync(0xffffffffu, tm1, 2));
        float mn0 = fmaxf(m0, tm0), mn1 = fmaxf(m1, tm1);
        float al0 = __expf(m0 - mn0), al1 = __expf(m1 - mn1);
        m0 = mn0; m1 = mn1;
        float s0 = 0.f, s1 = 0.f;
        uint32_t plo[8], phi[8];
#pragma unroll
        for (int nb = 0; nb < 8; nb++) {
            float p0 = __expf(sacc[nb * 4 + 0] - mn0);
            float p1 = __expf(sacc[nb * 4 + 1] - mn0);
            float p2 = __expf(sacc[nb * 4 + 2] - mn1);
            float p3 = __expf(sacc[nb * 4 + 3] - mn1);
            s0 += p0 + p1; s1 += p2 + p3;
            plo[nb] = bfpack(p0, p1);
            phi[nb] = bfpack(p2, p3);
        }
        s0 += __shfl_xor_sync(0xffffffffu, s0, 1);
        s0 += __shfl_xor_sync(0xffffffffu, s0, 2);
        s1 += __shfl_xor_sync(0xffffffffu, s1, 1);
        s1 += __shfl_xor_sync(0xffffffffu, s1, 2);
        l0 = l0 * al0 + s0;
        l1 = l1 * al1 + s1;
#pragma unroll
        for (int nb = 0; nb < 8; nb++) {
            oacc[nb * 4 + 0] *= al0; oacc[nb * 4 + 1] *= al0;
            oacc[nb * 4 + 2] *= al1; oacc[nb * 4 + 3] *= al1;
        }

#pragma unroll
        for (int kc = 0; kc < 4; kc++) {
            uint32_t pa[4] = {plo[2 * kc], phi[2 * kc], plo[2 * kc + 1], phi[2 * kc + 1]};
#pragma unroll
            for (int nb2 = 0; nb2 < 4; nb2++) {
                uint32_t b0, b1, b2, b3;
                ldsm4(b0, b1, b2, b3, vls + bo + nb2 * (16 * KVS * 2) + kc * 32);
                mma_bf16(oacc + (2 * nb2) * 4,     pa, b0, b1);
                mma_bf16(oacc + (2 * nb2 + 1) * 4, pa, b2, b3);
            }
        }

        __syncthreads();
        if (kt < 14) {
            int k0 = (kt + 2) * 64;
            uint32_t nb_ = (kt & 1) * BUFE * 2;
            CP16(kd0 + nb_, Kb + (size_t)(k0 + kr0) * 64 + kg0 * 8);
            CP16(kd1 + nb_, Kb + (size_t)(k0 + kr1) * 64 + kg1 * 8);
            CP16(vd0 + nb_, Vb + (size_t)kr0 * Lseq + k0 + kg0 * 8);
            CP16(vd1 + nb_, Vb + (size_t)kr1 * Lseq + k0 + kg1 * 8);
        }
        CP_COMMIT();
    }

    // epilogue: O / l -> att (b, l, head*64+c) bf16
    float inv0 = 1.0f / l0, inv1 = 1.0f / l1;
    int bb = n >> 3, head = n & 7;
    int qg0 = q0 + w * 16 + g, qg1 = qg0 + 8;
#pragma unroll
    for (int nb = 0; nb < 8; nb++) {
        int c = head * 64 + nb * 8 + 2 * r;
        *(uint32_t*)&att[((size_t)bb * Lseq + qg0) * 512 + c] =
            bfpack(oacc[nb * 4 + 0] * inv0, oacc[nb * 4 + 1] * inv0);
        *(uint32_t*)&att[((size_t)bb * Lseq + qg1) * 512 + c] =
            bfpack(oacc[nb * 4 + 2] * inv1, oacc[nb * 4 + 3] * inv1);
    }
}

// ---------------- K3/K5: bf16 mma GEMM (64 x Kdim) + bias + residual + channel LN ----------------
// grid (16 Ltiles of 64, 16 b); 256 threads; warp = (wm 0-3 m-block, wn 0-1 l-half)
__global__ __launch_bounds__(256) void gemm_ln_kernel(
    const __nv_bfloat16* __restrict__ X,   // (b, 1024, Kdim) bf16
    const __nv_bfloat16* __restrict__ Wg,  // (64, Kdim) bf16
    const float* __restrict__ bias, const float* __restrict__ res,  // res (b,64,1024) f32
    const float* __restrict__ gam, const float* __restrict__ bet,
    float* __restrict__ outF,              // (b,64,1024) f32
    __nv_bfloat16* __restrict__ outH,      // (b,1024,64) bf16 or nullptr
    int Kdim)
{
    __shared__ __align__(16) char SM[36864];
    __shared__ float ps1[4 * 64], ps2[4 * 64], mu_s[64], iv_s[64];
    __shared__ float gs[64], bts[64], bss[64];
    int tid = threadIdx.x, w = tid >> 5, lane = tid & 31;
    int wm = w >> 1, wn = w & 1;
    int g = lane >> 2, r = lane & 3;
    int l0 = blockIdx.x * 64;
    int b  = blockIdx.y;
    int nch = Kdim >> 6;

    if (tid < 64) { gs[tid] = gam[tid]; bts[tid] = bet[tid]; bss[tid] = bias[tid]; }

    uint32_t asb = smem_u32(SM);
    uint32_t bsb = asb + 18432;
    uint32_t a_off = (uint32_t)(((wm * 16 + (lane & 15)) * KVS + ((lane >> 4) << 3)) * 2);
    uint32_t b_off = (uint32_t)(((wn * 32 + (((lane >> 4) & 1) << 3) + (lane & 7)) * KVS +
                                 (((lane >> 3) & 1) << 3)) * 2);
    int sr0 = tid >> 3, sg0 = tid & 7;           // staging row/granule (2 per thread)
    int sr1 = (tid + 256) >> 3, sg1 = (tid + 256) & 7;
    uint32_t ad0 = asb + (sr0 * KVS + sg0 * 8) * 2;
    uint32_t ad1 = asb + (sr1 * KVS + sg1 * 8) * 2;
    uint32_t bd0 = bsb + (sr0 * KVS + sg0 * 8) * 2;
    uint32_t bd1 = bsb + (sr1 * KVS + sg1 * 8) * 2;
    const __nv_bfloat16* Xb = X + (size_t)b * Lseq * Kdim;

#pragma unroll
    for (int t = 0; t < 2; t++) {
        int cb = t * 64;
        uint32_t bo = t * 9216;
        CP16(ad0 + bo, Wg + (size_t)sr0 * Kdim + cb + sg0 * 8);
        CP16(ad1 + bo, Wg + (size_t)sr1 * Kdim + cb + sg1 * 8);
        CP16(bd0 + bo, Xb + (size_t)(l0 + sr0) * Kdim + cb + sg0 * 8);
        CP16(bd1 + bo, Xb + (size_t)(l0 + sr1) * Kdim + cb + sg1 * 8);
        CP_COMMIT();
    }

    float acc[16];
#pragma unroll
    for (int i = 0; i < 16; i++) acc[i] = 0.f;

    for (int c = 0; c < nch; c++) {
        CP_WAIT1();
        __syncthreads();
        uint32_t bo = (c & 1) * 9216;
        uint32_t ab = asb + bo + a_off;
        uint32_t bb2 = bsb + bo + b_off;
#pragma unroll
        for (int kc = 0; kc < 4; kc++) {
            uint32_t af0, af1, af2, af3;
            ldsm4(af0, af1, af2, af3, ab + kc * 32);
            uint32_t af[4] = {af0, af1, af2, af3};
            uint32_t b0, b1, b2, b3;
            ldsm4(b0, b1, b2, b3, bb2 + kc * 32);
            mma_bf16(acc + 0, af, b0, b1);
            mma_bf16(acc + 4, af, b2, b3);
            ldsm4(b0, b1, b2, b3, bb2 + 16 * KVS * 2 + kc * 32);
            mma_bf16(acc + 8,  af, b0, b1);
            mma_bf16(acc + 12, af, b2, b3);
        }
        __syncthreads();
        if (c + 2 < nch) {
            int cb = (c + 2) * 64;
            uint32_t nb_ = (c & 1) * 9216;
            CP16(ad0 + nb_, Wg + (size_t)sr0 * Kdim + cb + sg0 * 8);
            CP16(ad1 + nb_, Wg + (size_t)sr1 * Kdim + cb + sg1 * 8);
            CP16(bd0 + nb_, Xb + (size_t)(l0 + sr0) * Kdim + cb + sg0 * 8);
            CP16(bd1 + nb_, Xb + (size_t)(l0 + sr1) * Kdim + cb + sg1 * 8);
        }
        CP_COMMIT();
    }
    __syncthreads();   // done with smem buffers; reuse as T / R

    float* T = (float*)SM;                 // [64][68] accum+bias
    float* R = (float*)(SM + 18432);       // [64][68] residual
    {
        float bv0 = bss[wm * 16 + g], bv1 = bss[wm * 16 + g + 8];
#pragma unroll
        for (int p = 0; p < 2; p++)
#pragma unroll
            for (int blk = 0; blk < 2; blk++) {
                int lb = wn * 32 + p * 16 + blk * 8 + 2 * r;
                int i = (p * 2 + blk) * 4;
                *(float2*)&T[(wm * 16 + g) * 68 + lb]     = make_float2(acc[i] + bv0, acc[i + 1] + bv0);
                *(float2*)&T[(wm * 16 + g + 8) * 68 + lb] = make_float2(acc[i + 2] + bv1, acc[i + 3] + bv1);
            }
    }
    for (int e = tid; e < 1024; e += 256) {
        int row = e >> 4, sg = e & 15;
        *(float4*)&R[row * 68 + sg * 4] =
            *(const float4*)&res[((size_t)b * 64 + row) * Lseq + l0 + sg * 4];
    }
    __syncthreads();

    {
        int l = tid & 63, p = tid >> 6;
        float s1 = 0.f, s2 = 0.f;
#pragma unroll
        for (int ch = p * 16; ch < p * 16 + 16; ch++) {
            float v = T[ch * 68 + l] + R[ch * 68 + l];
            s1 += v; s2 += v * v;
        }
        ps1[p * 64 + l] = s1; ps2[p * 64 + l] = s2;
    }
    __syncthreads();
    if (tid < 64) {
        float s1 = ps1[tid] + ps1[64 + tid] + ps1[128 + tid] + ps1[192 + tid];
        float s2 = ps2[tid] + ps2[64 + tid] + ps2[128 + tid] + ps2[192 + tid];
        float mu = s1 * (1.0f / 64.0f);
        float var = s2 * (1.0f / 64.0f) - mu * mu;
        mu_s[tid] = mu;
        iv_s[tid] = rsqrtf(var + 1e-5f);
    }
    __syncthreads();

    {   // fp32 out (b, c, l)
        int ch = tid >> 2, ls = (tid & 3) * 16;
        float gv = gs[ch], bv = bts[ch];
        float* op = outF + ((size_t)b * 64 + ch) * Lseq + l0 + ls;
#pragma unroll
        for (int j = 0; j < 16; j += 4) {
            float4 ov;
            float* tp = &T[ch * 68 + ls + j];
            float* rp = &R[ch * 68 + ls + j];
            ov.x = (tp[0] + rp[0] - mu_s[ls + j + 0]) * iv_s[ls + j + 0] * gv + bv;
            ov.y = (tp[1] + rp[1] - mu_s[ls + j + 1]) * iv_s[ls + j + 1] * gv + bv;
            ov.z = (tp[2] + rp[2] - mu_s[ls + j + 2]) * iv_s[ls + j + 2] * gv + bv;
            ov.w = (tp[3] + rp[3] - mu_s[ls + j + 3]) * iv_s[ls + j + 3] * gv + bv;
            *(float4*)(op + j) = ov;
        }
    }
    if (outH) {   // bf16 out (b, l, c)
        int l = tid >> 2, cs = (tid & 3) * 16;
        float mu = mu_s[l], iv = iv_s[l];
        __nv_bfloat16* hp = outH + ((size_t)b * Lseq + l0 + l) * 64 + cs;
#pragma unroll
        for (int c = 0; c < 16; c += 2) {
            float v0 = (T[(cs + c) * 68 + l] + R[(cs + c) * 68 + l] - mu) * iv * gs[cs + c] + bts[cs + c];
            float v1 = (T[(cs + c + 1) * 68 + l] + R[(cs + c + 1) * 68 + l] - mu) * iv * gs[cs + c + 1] + bts[cs + c + 1];
            *(uint32_t*)(hp + c) = bfpack(v0, v1);
        }
    }
}

// ---------------- K4: FFN up-projection bf16 mma (64 out-block x K=64) + ReLU ----------------
// grid (16 Ltiles, 4 m-blocks, 16 b)
__global__ __launch_bounds__(256) void ffn1_mma(
    const __nv_bfloat16* __restrict__ X,   // g_Yh (b, 1024, 64)
    const __nv_bfloat16* __restrict__ Wg,  // g_W1 (256, 64)
    const float* __restrict__ bias,
    __nv_bfloat16* __restrict__ H)         // (b, 1024, 256)
{
    __shared__ __align__(16) __nv_bfloat16 As[64 * KVS];
    __shared__ __align__(16) __nv_bfloat16 Bs[64 * KVS];
    __shared__ float T[64 * 68];
    __shared__ float bss[64];
    int tid = threadIdx.x, w = tid >> 5, lane = tid & 31;
    int wm = w >> 1, wn = w & 1;
    int g = lane >> 2, r = lane & 3;
    int l0 = blockIdx.x * 64;
    int mb = blockIdx.y;
    int b  = blockIdx.z;

    if (tid < 64) bss[tid] = bias[mb * 64 + tid];
    for (int e = tid; e < 512; e += 256) {
        int row = e >> 3, kg = e & 7;
        *(uint4*)&As[row * KVS + kg * 8] =
            *(const uint4*)&Wg[(size_t)(mb * 64 + row) * 64 + kg * 8];
        *(uint4*)&Bs[row * KVS + kg * 8] =
            *(const uint4*)&X[((size_t)b * Lseq + l0 + row) * 64 + kg * 8];
    }
    __syncthreads();

    uint32_t ab = smem_u32(As) + (((wm * 16 + (lane & 15)) * KVS + ((lane >> 4) << 3)) * 2);
    uint32_t bb2 = smem_u32(Bs) + (((wn * 32 + (((lane >> 4) & 1) << 3) + (lane & 7)) * KVS +
                                    (((lane >> 3) & 1) << 3)) * 2);
    float acc[16];
#pragma unroll
    for (int i = 0; i < 16; i++) acc[i] = 0.f;
#pragma unroll
    for (int kc = 0; kc < 4; kc++) {
        uint32_t af0, af1, af2, af3;
        ldsm4(af0, af1, af2, af3, ab + kc * 32);
        uint32_t af[4] = {af0, af1, af2, af3};
        uint32_t b0, b1, b2, b3;
        ldsm4(b0, b1, b2, b3, bb2 + kc * 32);
        mma_bf16(acc + 0, af, b0, b1);
        mma_bf16(acc + 4, af, b2, b3);
        ldsm4(b0, b1, b2, b3, bb2 + 16 * KVS * 2 + kc * 32);
        mma_bf16(acc + 8,  af, b0, b1);
        mma_bf16(acc + 12, af, b2, b3);
    }
    __syncthreads();
    {
        float bv0 = bss[wm * 16 + g], bv1 = bss[wm * 16 + g + 8];
#pragma unroll
        for (int p = 0; p < 2; p++)
#pragma unroll
            for (int blk = 0; blk < 2; blk++) {
                int lb = wn * 32 + p * 16 + blk * 8 + 2 * r;
                int i = (p * 2 + blk) * 4;
                *(float2*)&T[(wm * 16 + g) * 68 + lb]     = make_float2(acc[i] + bv0, acc[i + 1] + bv0);
                *(float2*)&T[(wm * 16 + g + 8) * 68 + lb] = make_float2(acc[i + 2] + bv1, acc[i + 3] + bv1);
            }
    }
    __syncthreads();
    {
        int l = tid >> 2, cs = (tid & 3) * 16;
        __nv_bfloat16* hp = H + ((size_t)b * Lseq + l0 + l) * 256 + mb * 64 + cs;
#pragma unroll
        for (int c = 0; c < 16; c += 2) {
            float v0 = fmaxf(T[(cs + c) * 68 + l], 0.f);
            float v1 = fmaxf(T[(cs + c + 1) * 68 + l], 0.f);
            *(uint32_t*)(hp + c) = bfpack(v0, v1);
        }
    }
}

// ---------------- launch ----------------
extern "C" void kernel_launch(void* const* d_in, const int* in_sizes, int n_in,
                              void* d_out, int out_size)
{
    const float* q       = (const float*)d_in[0];
    const float* wq_pw   = (const float*)d_in[1];
    const float* wq_gate = (const float*)d_in[2];
    const float* wq_dw3  = (const float*)d_in[3];
    const float* wq_dw15 = (const float*)d_in[4];
    const float* wk_pw   = (const float*)d_in[5];
    const float* wk_gate = (const float*)d_in[6];
    const float* wk_dw3  = (const float*)d_in[7];
    const float* wk_dw15 = (const float*)d_in[8];
    const float* wv_pw   = (const float*)d_in[9];
    const float* wv_gate = (const float*)d_in[10];
    const float* wv_dw3  = (const float*)d_in[11];
    const float* wv_dw15 = (const float*)d_in[12];
    const float* w_unify = (const float*)d_in[13];
    const float* b_unify = (const float*)d_in[14];
    const float* ln1_g   = (const float*)d_in[15];
    const float* ln1_b   = (const float*)d_in[16];
    const float* ln2_g   = (const float*)d_in[17];
    const float* ln2_b   = (const float*)d_in[18];
    const float* ffn_w1  = (const float*)d_in[19];
    const float* ffn_b1  = (const float*)d_in[20];
    const float* ffn_w2  = (const float*)d_in[21];
    const float* ffn_b2  = (const float*)d_in[22];
    float* out = (float*)d_out;

    void *pPW, *pWF, *pQ, *pK, *pV, *pATT, *pY, *pYh, *pH, *pWu, *pW1, *pW2;
    cudaGetSymbolAddress(&pPW, g_PW);
    cudaGetSymbolAddress(&pWF, g_WF);
    cudaGetSymbolAddress(&pQ, g_Q);
    cudaGetSymbolAddress(&pK, g_K);
    cudaGetSymbolAddress(&pV, g_V);
    cudaGetSymbolAddress(&pATT, g_ATT);
    cudaGetSymbolAddress(&pY, g_Y);
    cudaGetSymbolAddress(&pYh, g_Yh);
    cudaGetSymbolAddress(&pH, g_H);
    cudaGetSymbolAddress(&pWu, g_Wu);
    cudaGetSymbolAddress(&pW1, g_W1);
    cudaGetSymbolAddress(&pW2, g_W2);

    cudaFuncSetAttribute(qkv_kernel, cudaFuncAttributeMaxDynamicSharedMemorySize, 65536);

    combine_kernel<<<6, 256>>>(
        wq_pw, wq_gate, wq_dw3, wq_dw15,
        wk_pw, wk_gate, wk_dw3, wk_dw15,
        wv_pw, wv_gate, wv_dw3, wv_dw15,
        (float*)pPW, (float*)pWF);

    convw_kernel<<<256, 256>>>(w_unify, ffn_w1, ffn_w2);

    qkv_kernel<<<dim3(8, 48, 16), 256, 65536>>>(
        q, (const float*)pPW, (const float*)pWF,
        (__nv_bfloat16*)pQ, (__nv_bfloat16*)pK, (__nv_bfloat16*)pV);

    attn_bf16<<<dim3(8, 128), 256>>>(
        (const __nv_bfloat16*)pQ, (const __nv_bfloat16*)pK,
        (const __nv_bfloat16*)pV, (__nv_bfloat16*)pATT);

    gemm_ln_kernel<<<dim3(16, 16), 256>>>(
        (const __nv_bfloat16*)pATT, (const __nv_bfloat16*)pWu,
        b_unify, q, ln1_g, ln1_b,
        (float*)pY, (__nv_bfloat16*)pYh, 512);

    ffn1_mma<<<dim3(16, 4, 16), 256>>>(
        (const __nv_bfloat16*)pYh, (const __nv_bfloat16*)pW1,
        ffn_b1, (__nv_bfloat16*)pH);

    gemm_ln_kernel<<<dim3(16, 16), 256>>>(
        (const __nv_bfloat16*)pH, (const __nv_bfloat16*)pW2,
        ffn_b2, (const float*)pY, ln2_g, ln2_b,
        out, (__nv_bfloat16*)nullptr, 256);
}